// round 7
// baseline (speedup 1.0000x reference)
#include <cuda_runtime.h>

// ---------------------------------------------------------------------------
// FrequencyAwareEmbedding, round 7.  TWO launches:
//   stage_b : blocks [0,391)   build bucket-3/4 row lists, in-kernel barrier,
//             then project (131 -> emb3@W3+b3, 260 -> emb4@W4+b4).
//             blocks [391,391+781) grid-stride copy of bucket-0..2 rows with
//             4-way front-batched loads (MLP=4). Total 1172 blocks ≈ 2 waves.
//   gather  : out[t] = g_all[x[t]], 8 tokens / 8-thread group (MLP=8);
//             resets counters for the next graph replay.
// ---------------------------------------------------------------------------

#define NROWS_MAX 100000
#define ODIM 32

#define NBUILD 391          // ceil(100000/256)
#define NB51   131          // build blocks that then project bucket 3
#define NBCOPY 781          // copy blocks (grid-stride, 4-way batched)

__device__ __align__(256) float g_all[NROWS_MAX * ODIM];
__device__ int g_list3[NROWS_MAX];
__device__ int g_list4[NROWS_MAX];
__device__ int g_cnt[2];        // zero-init at load; re-zeroed by gather
__device__ int g_build_done;    // idem

// --- build one 256-row tile of the bucket-3/4 lists (block-aggregated) ---
__device__ __forceinline__ void build_tile(const int* __restrict__ bucket,
                                           int rows, int tile)
{
    __shared__ int woff3[8], woff4[8];
    __shared__ int base3, base4;

    int r = tile * 256 + threadIdx.x;
    int bk = (r < rows) ? __ldg(&bucket[r]) : -1;
    int lane = threadIdx.x & 31;
    int wid  = threadIdx.x >> 5;

    unsigned m3 = __ballot_sync(0xffffffffu, bk == 3);
    unsigned m4 = __ballot_sync(0xffffffffu, bk == 4);

    if (lane == 0) { woff3[wid] = __popc(m3); woff4[wid] = __popc(m4); }
    __syncthreads();

    if (threadIdx.x == 0) {
        int t3 = 0, t4 = 0;
        #pragma unroll
        for (int i = 0; i < 8; ++i) {
            int c3 = woff3[i]; woff3[i] = t3; t3 += c3;
            int c4 = woff4[i]; woff4[i] = t4; t4 += c4;
        }
        base3 = (t3 > 0) ? atomicAdd(&g_cnt[0], t3) : 0;
        base4 = (t4 > 0) ? atomicAdd(&g_cnt[1], t4) : 0;
    }
    __syncthreads();

    unsigned lt = (1u << lane) - 1u;
    if (bk == 3) g_list3[base3 + woff3[wid] + __popc(m3 & lt)] = r;
    if (bk == 4) g_list4[base4 + woff4[wid] + __popc(m4 & lt)] = r;
}

// --- project 8 same-bucket rows per warp (lane j = output col j) ---
template <int K>
__device__ __forceinline__ void project_impl(const float* __restrict__ emb,
                                             const float* __restrict__ W,
                                             const float* __restrict__ b,
                                             const int*   __restrict__ list,
                                             int cnt,
                                             float*       __restrict__ out,
                                             int wid, int nw)
{
    constexpr int CH = (K + 31) / 32;
    int lane = threadIdx.x & 31;

    float bias = b[lane];

    for (int base = wid * 8; base < cnt; base += nw * 8) {
        int nvalid = cnt - base;
        if (nvalid > 8) nvalid = 8;

        int rows[8];
        #pragma unroll
        for (int r = 0; r < 8; ++r)
            rows[r] = __ldg(&list[base + (r < nvalid ? r : 0)]);

        float ev[8][CH];
        #pragma unroll
        for (int r = 0; r < 8; ++r) {
            #pragma unroll
            for (int ch = 0; ch < CH; ++ch) {
                int k = ch * 32 + lane;
                ev[r][ch] = (k < K) ? __ldg(&emb[(size_t)rows[r] * K + k]) : 0.0f;
            }
        }

        float acc[8];
        #pragma unroll
        for (int r = 0; r < 8; ++r) acc[r] = bias;

        #pragma unroll
        for (int ch = 0; ch < CH; ++ch) {
            const int kmax = (K - ch * 32 < 32) ? (K - ch * 32) : 32;
            #pragma unroll 8
            for (int src = 0; src < kmax; ++src) {
                float w = __ldg(&W[(ch * 32 + src) * 32 + lane]);
                #pragma unroll
                for (int r = 0; r < 8; ++r) {
                    float e = __shfl_sync(0xffffffffu, ev[r][ch], src);
                    acc[r] = fmaf(e, w, acc[r]);
                }
            }
        }

        #pragma unroll
        for (int r = 0; r < 8; ++r)
            if (r < nvalid)
                out[(size_t)rows[r] * ODIM + lane] = acc[r];
    }
}

// --- grid-stride copy of buckets 0..2, 4 row-lanes per iteration (MLP=4) ---
__device__ __forceinline__ void copy_impl(const int*    __restrict__ bucket,
                                          const float4* __restrict__ e0,
                                          const float4* __restrict__ e1,
                                          const float4* __restrict__ e2,
                                          float4*       __restrict__ out,
                                          int rows, int gid0, int stride)
{
    const int total = rows * 8;           // one lane = one float4 of one row

    for (int g = gid0; g < total; g += stride * 4) {
        int  gg[4];
        bool ok[4];
        int  bk[4];

        #pragma unroll
        for (int i = 0; i < 4; ++i) {
            gg[i] = g + i * stride;
            ok[i] = gg[i] < total;
        }

        // front-batched bucket loads (4 independent)
        #pragma unroll
        for (int i = 0; i < 4; ++i)
            bk[i] = ok[i] ? __ldg(&bucket[gg[i] >> 3]) : 3;

        // front-batched data loads (4 independent, predicated)
        float4 v[4];
        #pragma unroll
        for (int i = 0; i < 4; ++i) {
            ok[i] = ok[i] && (bk[i] <= 2);
            const float4* t = (bk[i] == 0) ? e0 : ((bk[i] == 1) ? e1 : e2);
            if (ok[i])
                v[i] = __ldg(&t[(size_t)(gg[i] >> 3) * 8 + (gg[i] & 7)]);
        }

        #pragma unroll
        for (int i = 0; i < 4; ++i)
            if (ok[i])
                out[(size_t)(gg[i] >> 3) * 8 + (gg[i] & 7)] = v[i];
    }
}

__global__ void stage_b(const int*    __restrict__ bucket,
                        const float4* __restrict__ e0,
                        const float4* __restrict__ e1,
                        const float4* __restrict__ e2,
                        const float*  __restrict__ emb3,
                        const float*  __restrict__ W3,
                        const float*  __restrict__ b3,
                        const float*  __restrict__ emb4,
                        const float*  __restrict__ W4,
                        const float*  __restrict__ b4,
                        float*        __restrict__ all_f,
                        int rows)
{
    if (blockIdx.x < NBUILD) {
        // ---- build phase ----
        build_tile(bucket, rows, blockIdx.x);

        __threadfence();
        __syncthreads();
        if (threadIdx.x == 0) {
            atomicAdd(&g_build_done, 1);
            while (atomicAdd(&g_build_done, 0) < NBUILD) { }
        }
        __syncthreads();
        __threadfence();

        // ---- projection phase (same blocks) ----
        int warp = threadIdx.x >> 5;
        if (blockIdx.x < NB51) {
            int wid = blockIdx.x * 8 + warp;
            project_impl<51>(emb3, W3, b3, g_list3, g_cnt[0], all_f,
                             wid, NB51 * 8);
        } else {
            int wid = (blockIdx.x - NB51) * 8 + warp;
            project_impl<102>(emb4, W4, b4, g_list4, g_cnt[1], all_f,
                              wid, (NBUILD - NB51) * 8);
        }
    } else {
        int gid0   = (blockIdx.x - NBUILD) * 256 + threadIdx.x;
        int stride = NBCOPY * 256;
        copy_impl(bucket, e0, e1, e2, (float4*)all_f, rows, gid0, stride);
    }
}

// 8-thread group handles EIGHT tokens (MLP=8). Resets counters for replay.
__global__ void gather_kernel(const int4*   __restrict__ x4,
                              const float4* __restrict__ tab,
                              float4*       __restrict__ out,
                              int Tg)
{
    if (blockIdx.x == 0 && threadIdx.x == 0) {
        g_cnt[0] = 0; g_cnt[1] = 0; g_build_done = 0;
    }

    int gid = blockIdx.x * blockDim.x + threadIdx.x;
    int grp = gid >> 3;
    if (grp >= Tg) return;
    int c = gid & 7;

    int4 ia = __ldg(&x4[(size_t)grp * 2 + 0]);
    int4 ib = __ldg(&x4[(size_t)grp * 2 + 1]);

    float4 v0 = __ldg(&tab[(size_t)ia.x * 8 + c]);
    float4 v1 = __ldg(&tab[(size_t)ia.y * 8 + c]);
    float4 v2 = __ldg(&tab[(size_t)ia.z * 8 + c]);
    float4 v3 = __ldg(&tab[(size_t)ia.w * 8 + c]);
    float4 v4 = __ldg(&tab[(size_t)ib.x * 8 + c]);
    float4 v5 = __ldg(&tab[(size_t)ib.y * 8 + c]);
    float4 v6 = __ldg(&tab[(size_t)ib.z * 8 + c]);
    float4 v7 = __ldg(&tab[(size_t)ib.w * 8 + c]);

    size_t base = (size_t)grp * 64 + c;
    __stcs(&out[base +  0], v0);
    __stcs(&out[base +  8], v1);
    __stcs(&out[base + 16], v2);
    __stcs(&out[base + 24], v3);
    __stcs(&out[base + 32], v4);
    __stcs(&out[base + 40], v5);
    __stcs(&out[base + 48], v6);
    __stcs(&out[base + 56], v7);
}

extern "C" void kernel_launch(void* const* d_in, const int* in_sizes, int n_in,
                              void* d_out, int out_size)
{
    const int*   x      = (const int*)  d_in[0];
    const int*   bucket = (const int*)  d_in[1];
    const float* emb0   = (const float*)d_in[2];
    const float* emb1   = (const float*)d_in[3];
    const float* emb2   = (const float*)d_in[4];
    const float* emb3   = (const float*)d_in[5];
    const float* emb4   = (const float*)d_in[6];
    const float* W3     = (const float*)d_in[7];
    const float* b3     = (const float*)d_in[8];
    const float* W4     = (const float*)d_in[9];
    const float* b4     = (const float*)d_in[10];

    const int T    = in_sizes[0];          // 1,048,576 tokens (multiple of 8)
    const int rows = in_sizes[1];          // 100,000

    float* all_f;
    cudaGetSymbolAddress((void**)&all_f, g_all);

    stage_b<<<NBUILD + NBCOPY, 256>>>(
        bucket, (const float4*)emb0, (const float4*)emb1, (const float4*)emb2,
        emb3, W3, b3, emb4, W4, b4, all_f, rows);

    const int Tg = T / 8;
    long long gthreads_total = (long long)Tg * 8;
    int gblocks = (int)((gthreads_total + 255) / 256);
    gather_kernel<<<gblocks, 256>>>((const int4*)x, (const float4*)all_f,
                                    (float4*)d_out, Tg);
}